// round 1
// baseline (speedup 1.0000x reference)
#include <cuda_runtime.h>
#include <math.h>

#define BB 2
#define LLEN 1024
#define HDIM 1024
#define NHEAD 16
#define HEADD 64
#define DIN 2048
#define NSTATE 16
#define QT 16

static const size_t U = (size_t)BB * LLEN * HDIM;  // 2097152

// scratch: q,k,v,ctx,t,x2,h (7U) + proj(4U) + ssm(2U) + dbc(B*L*96) + dt(2U) + scan(2U) + xf(U)
__device__ float g_buf[37945344];

// ---------------------------------------------------------------------------
// Generic SGEMM: C[M,N] = A[M,K] @ Bw[N,K]^T (+bias[n]) (+addsrc[M,N]) (+act)
// act: 0 = none, 1 = softplus
// ---------------------------------------------------------------------------
__global__ __launch_bounds__(256) void sgemm_kernel(
    const float* __restrict__ A, int lda,
    const float* __restrict__ Bw, int ldb,
    const float* __restrict__ bias,
    const float* __restrict__ addsrc,
    float* __restrict__ C,
    int M, int N, int K, int act)
{
    __shared__ float As[8][128];
    __shared__ float Bs[8][128];
    int t = threadIdx.x;
    int bm = blockIdx.y * 128;
    int bn = blockIdx.x * 128;
    int tx = t & 15, ty = t >> 4;
    int lrow = t >> 1;
    int lcol = (t & 1) * 4;
    float acc[8][8];
#pragma unroll
    for (int i = 0; i < 8; i++)
#pragma unroll
        for (int j = 0; j < 8; j++) acc[i][j] = 0.f;

    const float* Aptr = A + (size_t)(bm + lrow) * lda + lcol;
    const float* Bptr = Bw + (size_t)(bn + lrow) * ldb + lcol;
    bool bvalid = (bn + lrow) < N;

    for (int k0 = 0; k0 < K; k0 += 8) {
        float4 av = *(const float4*)(Aptr + k0);
        float4 bv = make_float4(0.f, 0.f, 0.f, 0.f);
        if (bvalid) bv = *(const float4*)(Bptr + k0);
        As[lcol + 0][lrow] = av.x; As[lcol + 1][lrow] = av.y;
        As[lcol + 2][lrow] = av.z; As[lcol + 3][lrow] = av.w;
        Bs[lcol + 0][lrow] = bv.x; Bs[lcol + 1][lrow] = bv.y;
        Bs[lcol + 2][lrow] = bv.z; Bs[lcol + 3][lrow] = bv.w;
        __syncthreads();
#pragma unroll
        for (int kk = 0; kk < 8; kk++) {
            float4 a0 = *(const float4*)(&As[kk][ty * 8]);
            float4 a1 = *(const float4*)(&As[kk][ty * 8 + 4]);
            float4 b0 = *(const float4*)(&Bs[kk][tx * 8]);
            float4 b1 = *(const float4*)(&Bs[kk][tx * 8 + 4]);
            float ar[8] = {a0.x, a0.y, a0.z, a0.w, a1.x, a1.y, a1.z, a1.w};
            float br[8] = {b0.x, b0.y, b0.z, b0.w, b1.x, b1.y, b1.z, b1.w};
#pragma unroll
            for (int i = 0; i < 8; i++)
#pragma unroll
                for (int j = 0; j < 8; j++)
                    acc[i][j] = fmaf(ar[i], br[j], acc[i][j]);
        }
        __syncthreads();
    }
#pragma unroll
    for (int i = 0; i < 8; i++) {
        int row = bm + ty * 8 + i;
#pragma unroll
        for (int j = 0; j < 8; j++) {
            int col = bn + tx * 8 + j;
            if (col < N) {
                float v = acc[i][j];
                if (bias) v += bias[col];
                if (addsrc) v += addsrc[(size_t)row * N + col];
                if (act == 1) v = (v > 20.f) ? v : log1pf(__expf(v));
                C[(size_t)row * N + col] = v;
            }
        }
    }
}

// ---------------------------------------------------------------------------
// Attention: one block per (16 q-rows, head, batch). Scores in dynamic smem.
// ---------------------------------------------------------------------------
__global__ __launch_bounds__(256) void attn_kernel(
    const float* __restrict__ q, const float* __restrict__ k,
    const float* __restrict__ v, const int* __restrict__ mask,
    float* __restrict__ ctx)
{
    extern __shared__ float sc[];            // QT * LLEN
    __shared__ float qs[QT][HEADD];
    __shared__ float rinv[QT];
    int t = threadIdx.x;
    int q0 = blockIdx.x * QT;
    int h = blockIdx.y;
    int b = blockIdx.z;
    size_t base = ((size_t)b * LLEN) * HDIM + h * HEADD;

    for (int i = t; i < QT * HEADD; i += 256) {
        int r = i >> 6, d = i & 63;
        qs[r][d] = q[base + (size_t)(q0 + r) * HDIM + d] * 0.125f; // 1/sqrt(64)
    }
    __syncthreads();

    // scores: each thread handles 4 keys, all 16 q-rows
#pragma unroll
    for (int s = 0; s < LLEN / 256; s++) {
        int kk = s * 256 + t;
        float accr[QT];
#pragma unroll
        for (int r = 0; r < QT; r++) accr[r] = 0.f;
        const float* kp = k + base + (size_t)kk * HDIM;
#pragma unroll 4
        for (int d4 = 0; d4 < 16; d4++) {
            float4 kv = *(const float4*)(kp + d4 * 4);
#pragma unroll
            for (int r = 0; r < QT; r++) {
                float4 qv = *(const float4*)(&qs[r][d4 * 4]);
                accr[r] = fmaf(kv.x, qv.x, accr[r]);
                accr[r] = fmaf(kv.y, qv.y, accr[r]);
                accr[r] = fmaf(kv.z, qv.z, accr[r]);
                accr[r] = fmaf(kv.w, qv.w, accr[r]);
            }
        }
        float mf = (float)mask[b * LLEN + kk];
#pragma unroll
        for (int r = 0; r < QT; r++) sc[r * LLEN + kk] = accr[r] + mf;
    }
    __syncthreads();

    // softmax: each warp handles 2 rows
    int warp = t >> 5, lane = t & 31;
    for (int r = warp; r < QT; r += 8) {
        float m = -1e30f;
        for (int i = lane; i < LLEN; i += 32) m = fmaxf(m, sc[r * LLEN + i]);
#pragma unroll
        for (int o = 16; o; o >>= 1) m = fmaxf(m, __shfl_xor_sync(0xffffffffu, m, o));
        float sum = 0.f;
        for (int i = lane; i < LLEN; i += 32) {
            float p = __expf(sc[r * LLEN + i] - m);
            sc[r * LLEN + i] = p;
            sum += p;
        }
#pragma unroll
        for (int o = 16; o; o >>= 1) sum += __shfl_xor_sync(0xffffffffu, sum, o);
        if (lane == 0) rinv[r] = 1.f / sum;
    }
    __syncthreads();

    // ctx: thread = (q-group of 4 rows, dim d); v load coalesced over d
    int d = t & 63;
    int qg = t >> 6;
    float a4[4] = {0.f, 0.f, 0.f, 0.f};
    const float* vp = v + base + d;
#pragma unroll 4
    for (int kk = 0; kk < LLEN; kk++) {
        float vv = vp[(size_t)kk * HDIM];
#pragma unroll
        for (int j = 0; j < 4; j++)
            a4[j] = fmaf(sc[(qg * 4 + j) * LLEN + kk], vv, a4[j]);
    }
#pragma unroll
    for (int j = 0; j < 4; j++) {
        int r = qg * 4 + j;
        ctx[base + (size_t)(q0 + r) * HDIM + d] = a4[j] * rinv[r];
    }
}

// ---------------------------------------------------------------------------
// Row reductions
// ---------------------------------------------------------------------------
__device__ __forceinline__ float block_sum_256(float v, float* sh)
{
#pragma unroll
    for (int o = 16; o; o >>= 1) v += __shfl_xor_sync(0xffffffffu, v, o);
    int lane = threadIdx.x & 31, w = threadIdx.x >> 5;
    if (lane == 0) sh[w] = v;
    __syncthreads();
    if (threadIdx.x == 0) {
        float r = sh[0];
#pragma unroll
        for (int i = 1; i < 8; i++) r += sh[i];
        sh[8] = r;
    }
    __syncthreads();
    float r = sh[8];
    __syncthreads();
    return r;
}

// x2 = LN(t)*lnw+lnb + hidden ; h = rmsnorm(x2)*mnw
__global__ __launch_bounds__(256) void ln_rms_kernel(
    const float* __restrict__ tin, const float* __restrict__ hidden,
    const float* __restrict__ lnw, const float* __restrict__ lnb,
    const float* __restrict__ mnw,
    float* __restrict__ x2, float* __restrict__ hout)
{
    __shared__ float sh[9];
    size_t row = blockIdx.x;
    int tid = threadIdx.x;
    const float* tp = tin + row * HDIM;
    float v[4]; float s = 0.f;
#pragma unroll
    for (int i = 0; i < 4; i++) { v[i] = tp[tid + 256 * i]; s += v[i]; }
    s = block_sum_256(s, sh);
    float mu = s * (1.f / 1024.f);
    float vs = 0.f;
#pragma unroll
    for (int i = 0; i < 4; i++) { float dd = v[i] - mu; vs += dd * dd; }
    vs = block_sum_256(vs, sh);
    float rstd = rsqrtf(vs * (1.f / 1024.f) + 1e-12f);
    float xv[4]; float ss = 0.f;
#pragma unroll
    for (int i = 0; i < 4; i++) {
        int c = tid + 256 * i;
        float z = (v[i] - mu) * rstd * lnw[c] + lnb[c] + hidden[row * HDIM + c];
        xv[i] = z; x2[row * HDIM + c] = z; ss += z * z;
    }
    ss = block_sum_256(ss, sh);
    float rr = rsqrtf(ss * (1.f / 1024.f) + 1e-6f);
#pragma unroll
    for (int i = 0; i < 4; i++) {
        int c = tid + 256 * i;
        hout[row * HDIM + c] = xv[i] * rr * mnw[c];
    }
}

__global__ __launch_bounds__(256) void rms_kernel(
    const float* __restrict__ x, const float* __restrict__ w,
    float* __restrict__ out)
{
    __shared__ float sh[9];
    size_t row = blockIdx.x;
    int tid = threadIdx.x;
    const float* xp = x + row * HDIM;
    float v[4]; float ss = 0.f;
#pragma unroll
    for (int i = 0; i < 4; i++) { v[i] = xp[tid + 256 * i]; ss += v[i] * v[i]; }
    ss = block_sum_256(ss, sh);
    float rr = rsqrtf(ss * (1.f / 1024.f) + 1e-6f);
#pragma unroll
    for (int i = 0; i < 4; i++) {
        int c = tid + 256 * i;
        out[row * HDIM + c] = v[i] * rr * w[c];
    }
}

// ---------------------------------------------------------------------------
// Depthwise causal conv (K=4) + SiLU + mask
// ---------------------------------------------------------------------------
__global__ __launch_bounds__(256) void conv_kernel(
    const float* __restrict__ proj, const int* __restrict__ mask,
    const float* __restrict__ cw, const float* __restrict__ cb,
    float* __restrict__ ssm)
{
    int idx = blockIdx.x * 256 + threadIdx.x;   // over B*L*DIN
    int d = idx & (DIN - 1);
    int l = (idx >> 11) & (LLEN - 1);
    int b = idx >> 21;
    float acc = cb[d];
#pragma unroll
    for (int j = 0; j < 4; j++) {
        int lp = l - 3 + j;
        if (lp >= 0) {
            float hv = proj[((size_t)(b * LLEN + lp)) * (2 * DIN) + d] *
                       (float)mask[b * LLEN + lp];
            acc = fmaf(hv, cw[d * 4 + j], acc);
        }
    }
    float sv = acc / (1.f + __expf(-acc));
    ssm[(size_t)idx] = sv * (float)mask[b * LLEN + l];
}

// ---------------------------------------------------------------------------
// Selective scan: thread per (b,d), 16-state recurrence, prefetched loads
// ---------------------------------------------------------------------------
__global__ __launch_bounds__(64) void scan_kernel(
    const float* __restrict__ dt, const float* __restrict__ dbc,
    const float* __restrict__ u, const float* __restrict__ proj,
    const float* __restrict__ Alog, const float* __restrict__ Dskip,
    float* __restrict__ outp)
{
    __shared__ float sBC[2][32];     // [buf][0:16)=B, [16:32)=C
    int b = blockIdx.x >> 5;
    int d = ((blockIdx.x & 31) << 6) + threadIdx.x;
    int t = threadIdx.x;
    float aA[NSTATE];
#pragma unroll
    for (int n = 0; n < NSTATE; n++) aA[n] = -__expf(Alog[d * NSTATE + n]);
    float dsk = Dskip[d];
    float s[NSTATE];
#pragma unroll
    for (int n = 0; n < NSTATE; n++) s[n] = 0.f;

    size_t tokbase = (size_t)b * LLEN;
    if (t < 32) sBC[0][t] = dbc[tokbase * 96 + 64 + t];
    float dtv = dt[tokbase * DIN + d];
    float uv = u[tokbase * DIN + d];
    float gv = proj[tokbase * (2 * DIN) + DIN + d];
    __syncthreads();

    for (int l = 0; l < LLEN; l++) {
        int cur = l & 1;
        float ndt = 0.f, nu = 0.f, ng = 0.f, nbc = 0.f;
        if (l + 1 < LLEN) {
            size_t tk = tokbase + l + 1;
            ndt = dt[tk * DIN + d];
            nu = u[tk * DIN + d];
            ng = proj[tk * (2 * DIN) + DIN + d];
            if (t < 32) nbc = dbc[tk * 96 + 64 + t];
        }
        float c = dtv * uv;
        float y = 0.f;
#pragma unroll
        for (int n = 0; n < NSTATE; n++) {
            float dA = __expf(dtv * aA[n]);
            s[n] = fmaf(dA, s[n], c * sBC[cur][n]);
            y = fmaf(s[n], sBC[cur][16 + n], y);
        }
        float sg = gv / (1.f + __expf(-gv));
        outp[(tokbase + l) * DIN + d] = (y + uv * dsk) * sg;
        if (t < 32 && l + 1 < LLEN) sBC[cur ^ 1][t] = nbc;
        dtv = ndt; uv = nu; gv = ng;
        __syncthreads();
    }
}

// ---------------------------------------------------------------------------
extern "C" void kernel_launch(void* const* d_in, const int* in_sizes, int n_in,
                              void* d_out, int out_size)
{
    const float* hidden = (const float*)d_in[0];
    const int*   mask   = (const int*)d_in[1];
    const float* Wq = (const float*)d_in[2];
    const float* bq = (const float*)d_in[3];
    const float* Wk = (const float*)d_in[4];
    const float* bk = (const float*)d_in[5];
    const float* Wv = (const float*)d_in[6];
    const float* bv = (const float*)d_in[7];
    const float* Wo = (const float*)d_in[8];
    const float* bo = (const float*)d_in[9];
    const float* lnw = (const float*)d_in[10];
    const float* lnb = (const float*)d_in[11];
    const float* mnw = (const float*)d_in[12];
    const float* inpw = (const float*)d_in[13];
    const float* convw = (const float*)d_in[14];
    const float* convb = (const float*)d_in[15];
    const float* xpw = (const float*)d_in[16];
    const float* dtpw = (const float*)d_in[17];
    const float* dtpb = (const float*)d_in[18];
    const float* Alog = (const float*)d_in[19];
    const float* Dsk = (const float*)d_in[20];
    const float* outpw = (const float*)d_in[21];
    const float* fnw = (const float*)d_in[22];
    float* out = (float*)d_out;

    float* buf = nullptr;
    cudaGetSymbolAddress((void**)&buf, g_buf);
    float* qb  = buf;
    float* kb  = buf + U;
    float* vb  = buf + 2 * U;
    float* ctx = buf + 3 * U;
    float* tb  = buf + 4 * U;
    float* x2  = buf + 5 * U;
    float* hb  = buf + 6 * U;
    float* proj = buf + 7 * U;                 // B*L*4096
    float* ssm  = buf + 11 * U;                // B*L*2048
    float* dbc  = buf + 13 * U;                // B*L*96
    float* dt   = dbc + (size_t)BB * LLEN * 96;
    float* scan = dt + 2 * U;
    float* xf   = scan + 2 * U;

    int M = BB * LLEN;
    dim3 thr(256);

    sgemm_kernel<<<dim3(HDIM / 128, M / 128), thr>>>(hidden, HDIM, Wq, HDIM, bq, nullptr, qb, M, HDIM, HDIM, 0);
    sgemm_kernel<<<dim3(HDIM / 128, M / 128), thr>>>(hidden, HDIM, Wk, HDIM, bk, nullptr, kb, M, HDIM, HDIM, 0);
    sgemm_kernel<<<dim3(HDIM / 128, M / 128), thr>>>(hidden, HDIM, Wv, HDIM, bv, nullptr, vb, M, HDIM, HDIM, 0);

    cudaFuncSetAttribute(attn_kernel, cudaFuncAttributeMaxDynamicSharedMemorySize, QT * LLEN * 4);
    attn_kernel<<<dim3(LLEN / QT, NHEAD, BB), thr, QT * LLEN * 4>>>(qb, kb, vb, mask, ctx);

    sgemm_kernel<<<dim3(HDIM / 128, M / 128), thr>>>(ctx, HDIM, Wo, HDIM, bo, hidden, tb, M, HDIM, HDIM, 0);
    ln_rms_kernel<<<M, thr>>>(tb, hidden, lnw, lnb, mnw, x2, hb);
    sgemm_kernel<<<dim3((2 * DIN) / 128, M / 128), thr>>>(hb, HDIM, inpw, HDIM, nullptr, nullptr, proj, M, 2 * DIN, HDIM, 0);
    conv_kernel<<<(BB * LLEN * DIN) / 256, thr>>>(proj, mask, convw, convb, ssm);
    sgemm_kernel<<<dim3(1, M / 128), thr>>>(ssm, DIN, xpw, DIN, nullptr, nullptr, dbc, M, 96, DIN, 0);
    sgemm_kernel<<<dim3(DIN / 128, M / 128), thr>>>(dbc, 96, dtpw, 64, dtpb, nullptr, dt, M, DIN, 64, 1);
    scan_kernel<<<64, 64>>>(dt, dbc, ssm, proj, Alog, Dsk, scan);
    sgemm_kernel<<<dim3(HDIM / 128, M / 128), thr>>>(scan, DIN, outpw, DIN, nullptr, x2, xf, M, HDIM, DIN, 0);
    rms_kernel<<<M, thr>>>(xf, fnw, out);
}

// round 3
// speedup vs baseline: 1.8054x; 1.8054x over previous
#include <cuda_runtime.h>
#include <math.h>
#include <stdint.h>

#define BB 2
#define LLEN 1024
#define HDIM 1024
#define NHEAD 16
#define HEADD 64
#define DIN 2048
#define NSTATE 16
#define QT 16

static const size_t U = (size_t)BB * LLEN * HDIM;  // 2097152

__device__ float g_buf[37945344];

// ===========================================================================
// tf32 helpers
// ===========================================================================
__device__ __forceinline__ float to_tf32(float x) {
    uint32_t r;
    asm("cvt.rna.tf32.f32 %0, %1;" : "=r"(r) : "f"(x));
    return __uint_as_float(r);
}

#define MMA_TF32(d, a, b) \
    asm volatile( \
        "mma.sync.aligned.m16n8k8.row.col.f32.tf32.tf32.f32 " \
        "{%0,%1,%2,%3}, {%4,%5,%6,%7}, {%8,%9}, {%0,%1,%2,%3};" \
        : "+f"((d)[0]), "+f"((d)[1]), "+f"((d)[2]), "+f"((d)[3]) \
        : "r"((a)[0]), "r"((a)[1]), "r"((a)[2]), "r"((a)[3]), \
          "r"((b)[0]), "r"((b)[1]))

#define SMP 20  // padded row stride (floats) for 16-k tiles: conflict-free frags

// ===========================================================================
// tf32 tensor GEMM: C[M,N] = A[M,K] @ Bw[N,K]^T (+bias) (+addsrc) (+act)
// 128x128 tile, BK=16 double-buffered, 8 warps (4x2), warp tile 32x64.
// ===========================================================================
__global__ __launch_bounds__(256, 2) void mm_kernel(
    const float* __restrict__ A, int lda,
    const float* __restrict__ Bw, int ldb,
    const float* __restrict__ bias,
    const float* __restrict__ addsrc,
    float* __restrict__ C,
    int M, int N, int K, int act)
{
    extern __shared__ float sm[];
    float* As = sm;                   // [2][128][SMP]
    float* Bs = sm + 2 * 128 * SMP;   // [2][128][SMP]

    int t = threadIdx.x;
    int lane = t & 31, wid = t >> 5;
    int wm = wid & 3, wn = wid >> 2;
    int gid = lane >> 2, tig = lane & 3;
    int bm = blockIdx.y * 128, bn = blockIdx.x * 128;

    int arow = t >> 1;
    int ahalf = (t & 1) * 8;
    const float* Ap = A + (size_t)(bm + arow) * lda + ahalf;
    const float* Bp = Bw + (size_t)(bn + arow) * ldb + ahalf;
    bool bvalid = (bn + arow) < N;

    float acc[2][8][4];
#pragma unroll
    for (int i = 0; i < 2; i++)
#pragma unroll
        for (int j = 0; j < 8; j++)
#pragma unroll
            for (int q = 0; q < 4; q++) acc[i][j][q] = 0.f;

    int nk = K >> 4;

    // prologue: chunk 0 -> buffer 0
    {
        float4 a0 = *(const float4*)(Ap);
        float4 a1 = *(const float4*)(Ap + 4);
        float4 b0 = make_float4(0.f, 0.f, 0.f, 0.f), b1 = b0;
        if (bvalid) { b0 = *(const float4*)(Bp); b1 = *(const float4*)(Bp + 4); }
        float* pa = As + arow * SMP + ahalf;
        float* pb = Bs + arow * SMP + ahalf;
        pa[0] = to_tf32(a0.x); pa[1] = to_tf32(a0.y); pa[2] = to_tf32(a0.z); pa[3] = to_tf32(a0.w);
        pa[4] = to_tf32(a1.x); pa[5] = to_tf32(a1.y); pa[6] = to_tf32(a1.z); pa[7] = to_tf32(a1.w);
        pb[0] = to_tf32(b0.x); pb[1] = to_tf32(b0.y); pb[2] = to_tf32(b0.z); pb[3] = to_tf32(b0.w);
        pb[4] = to_tf32(b1.x); pb[5] = to_tf32(b1.y); pb[6] = to_tf32(b1.z); pb[7] = to_tf32(b1.w);
    }
    __syncthreads();

    for (int c = 0; c < nk; c++) {
        int cur = c & 1;
        float4 na0, na1, nb0, nb1;
        bool pf = (c + 1) < nk;
        if (pf) {
            int k0 = (c + 1) << 4;
            na0 = *(const float4*)(Ap + k0);
            na1 = *(const float4*)(Ap + k0 + 4);
            nb0 = make_float4(0.f, 0.f, 0.f, 0.f); nb1 = nb0;
            if (bvalid) {
                nb0 = *(const float4*)(Bp + k0);
                nb1 = *(const float4*)(Bp + k0 + 4);
            }
        }

        const float* Ab = As + cur * 128 * SMP;
        const float* Bb = Bs + cur * 128 * SMP;
#pragma unroll
        for (int ks = 0; ks < 2; ks++) {
            int k8 = ks * 8 + tig;
            uint32_t af[2][4];
#pragma unroll
            for (int mm = 0; mm < 2; mm++) {
                int r0 = wm * 32 + mm * 16 + gid;
                af[mm][0] = __float_as_uint(Ab[r0 * SMP + k8]);
                af[mm][1] = __float_as_uint(Ab[(r0 + 8) * SMP + k8]);
                af[mm][2] = __float_as_uint(Ab[r0 * SMP + k8 + 4]);
                af[mm][3] = __float_as_uint(Ab[(r0 + 8) * SMP + k8 + 4]);
            }
            uint32_t bf[8][2];
#pragma unroll
            for (int nn = 0; nn < 8; nn++) {
                int n0 = wn * 64 + nn * 8 + gid;
                bf[nn][0] = __float_as_uint(Bb[n0 * SMP + k8]);
                bf[nn][1] = __float_as_uint(Bb[n0 * SMP + k8 + 4]);
            }
#pragma unroll
            for (int mm = 0; mm < 2; mm++)
#pragma unroll
                for (int nn = 0; nn < 8; nn++)
                    MMA_TF32(acc[mm][nn], af[mm], bf[nn]);
        }

        if (pf) {
            int nxt = cur ^ 1;
            float* pa = As + nxt * 128 * SMP + arow * SMP + ahalf;
            float* pb = Bs + nxt * 128 * SMP + arow * SMP + ahalf;
            pa[0] = to_tf32(na0.x); pa[1] = to_tf32(na0.y); pa[2] = to_tf32(na0.z); pa[3] = to_tf32(na0.w);
            pa[4] = to_tf32(na1.x); pa[5] = to_tf32(na1.y); pa[6] = to_tf32(na1.z); pa[7] = to_tf32(na1.w);
            pb[0] = to_tf32(nb0.x); pb[1] = to_tf32(nb0.y); pb[2] = to_tf32(nb0.z); pb[3] = to_tf32(nb0.w);
            pb[4] = to_tf32(nb1.x); pb[5] = to_tf32(nb1.y); pb[6] = to_tf32(nb1.z); pb[7] = to_tf32(nb1.w);
        }
        __syncthreads();
    }

    // epilogue: registers -> gmem directly
#pragma unroll
    for (int mm = 0; mm < 2; mm++) {
        int r0 = bm + wm * 32 + mm * 16 + gid;
#pragma unroll
        for (int nn = 0; nn < 8; nn++) {
            int col = bn + wn * 64 + nn * 8 + 2 * tig;
            if (col < N) {
                float v00 = acc[mm][nn][0], v01 = acc[mm][nn][1];
                float v10 = acc[mm][nn][2], v11 = acc[mm][nn][3];
                if (bias) {
                    float b0 = bias[col], b1 = bias[col + 1];
                    v00 += b0; v01 += b1; v10 += b0; v11 += b1;
                }
                size_t o0 = (size_t)r0 * N + col;
                size_t o1 = (size_t)(r0 + 8) * N + col;
                if (addsrc) {
                    v00 += addsrc[o0]; v01 += addsrc[o0 + 1];
                    v10 += addsrc[o1]; v11 += addsrc[o1 + 1];
                }
                if (act == 1) {
                    v00 = (v00 > 20.f) ? v00 : log1pf(__expf(v00));
                    v01 = (v01 > 20.f) ? v01 : log1pf(__expf(v01));
                    v10 = (v10 > 20.f) ? v10 : log1pf(__expf(v10));
                    v11 = (v11 > 20.f) ? v11 : log1pf(__expf(v11));
                }
                *(float2*)(C + o0) = make_float2(v00, v01);
                *(float2*)(C + o1) = make_float2(v10, v11);
            }
        }
    }
}

// ---------------------------------------------------------------------------
// Attention: one block per (16 q-rows, head, batch). Scores in dynamic smem.
// ---------------------------------------------------------------------------
__global__ __launch_bounds__(256) void attn_kernel(
    const float* __restrict__ q, const float* __restrict__ k,
    const float* __restrict__ v, const int* __restrict__ mask,
    float* __restrict__ ctx)
{
    extern __shared__ float sc[];            // QT * LLEN
    __shared__ float qs[QT][HEADD];
    __shared__ float rinv[QT];
    int t = threadIdx.x;
    int q0 = blockIdx.x * QT;
    int h = blockIdx.y;
    int b = blockIdx.z;
    size_t base = ((size_t)b * LLEN) * HDIM + h * HEADD;

    for (int i = t; i < QT * HEADD; i += 256) {
        int r = i >> 6, d = i & 63;
        qs[r][d] = q[base + (size_t)(q0 + r) * HDIM + d] * 0.125f;
    }
    __syncthreads();

#pragma unroll
    for (int s = 0; s < LLEN / 256; s++) {
        int kk = s * 256 + t;
        float accr[QT];
#pragma unroll
        for (int r = 0; r < QT; r++) accr[r] = 0.f;
        const float* kp = k + base + (size_t)kk * HDIM;
#pragma unroll 4
        for (int d4 = 0; d4 < 16; d4++) {
            float4 kv = *(const float4*)(kp + d4 * 4);
#pragma unroll
            for (int r = 0; r < QT; r++) {
                float4 qv = *(const float4*)(&qs[r][d4 * 4]);
                accr[r] = fmaf(kv.x, qv.x, accr[r]);
                accr[r] = fmaf(kv.y, qv.y, accr[r]);
                accr[r] = fmaf(kv.z, qv.z, accr[r]);
                accr[r] = fmaf(kv.w, qv.w, accr[r]);
            }
        }
        float mf = (float)mask[b * LLEN + kk];
#pragma unroll
        for (int r = 0; r < QT; r++) sc[r * LLEN + kk] = accr[r] + mf;
    }
    __syncthreads();

    int warp = t >> 5, lane = t & 31;
    for (int r = warp; r < QT; r += 8) {
        float m = -1e30f;
        for (int i = lane; i < LLEN; i += 32) m = fmaxf(m, sc[r * LLEN + i]);
#pragma unroll
        for (int o = 16; o; o >>= 1) m = fmaxf(m, __shfl_xor_sync(0xffffffffu, m, o));
        float sum = 0.f;
        for (int i = lane; i < LLEN; i += 32) {
            float p = __expf(sc[r * LLEN + i] - m);
            sc[r * LLEN + i] = p;
            sum += p;
        }
#pragma unroll
        for (int o = 16; o; o >>= 1) sum += __shfl_xor_sync(0xffffffffu, sum, o);
        if (lane == 0) rinv[r] = 1.f / sum;
    }
    __syncthreads();

    int d = t & 63;
    int qg = t >> 6;
    float a4[4] = {0.f, 0.f, 0.f, 0.f};
    const float* vp = v + base + d;
#pragma unroll 8
    for (int kk = 0; kk < LLEN; kk++) {
        float vv = vp[(size_t)kk * HDIM];
#pragma unroll
        for (int j = 0; j < 4; j++)
            a4[j] = fmaf(sc[(qg * 4 + j) * LLEN + kk], vv, a4[j]);
    }
#pragma unroll
    for (int j = 0; j < 4; j++) {
        int r = qg * 4 + j;
        ctx[base + (size_t)(q0 + r) * HDIM + d] = a4[j] * rinv[r];
    }
}

// ---------------------------------------------------------------------------
// Row reductions
// ---------------------------------------------------------------------------
__device__ __forceinline__ float block_sum_256(float v, float* sh)
{
#pragma unroll
    for (int o = 16; o; o >>= 1) v += __shfl_xor_sync(0xffffffffu, v, o);
    int lane = threadIdx.x & 31, w = threadIdx.x >> 5;
    if (lane == 0) sh[w] = v;
    __syncthreads();
    if (threadIdx.x == 0) {
        float r = sh[0];
#pragma unroll
        for (int i = 1; i < 8; i++) r += sh[i];
        sh[8] = r;
    }
    __syncthreads();
    float r = sh[8];
    __syncthreads();
    return r;
}

__global__ __launch_bounds__(256) void ln_rms_kernel(
    const float* __restrict__ tin, const float* __restrict__ hidden,
    const float* __restrict__ lnw, const float* __restrict__ lnb,
    const float* __restrict__ mnw,
    float* __restrict__ x2, float* __restrict__ hout)
{
    __shared__ float sh[9];
    size_t row = blockIdx.x;
    int tid = threadIdx.x;
    const float* tp = tin + row * HDIM;
    float v[4]; float s = 0.f;
#pragma unroll
    for (int i = 0; i < 4; i++) { v[i] = tp[tid + 256 * i]; s += v[i]; }
    s = block_sum_256(s, sh);
    float mu = s * (1.f / 1024.f);
    float vs = 0.f;
#pragma unroll
    for (int i = 0; i < 4; i++) { float dd = v[i] - mu; vs += dd * dd; }
    vs = block_sum_256(vs, sh);
    float rstd = rsqrtf(vs * (1.f / 1024.f) + 1e-12f);
    float xv[4]; float ss = 0.f;
#pragma unroll
    for (int i = 0; i < 4; i++) {
        int c = tid + 256 * i;
        float z = (v[i] - mu) * rstd * lnw[c] + lnb[c] + hidden[row * HDIM + c];
        xv[i] = z; x2[row * HDIM + c] = z; ss += z * z;
    }
    ss = block_sum_256(ss, sh);
    float rr = rsqrtf(ss * (1.f / 1024.f) + 1e-6f);
#pragma unroll
    for (int i = 0; i < 4; i++) {
        int c = tid + 256 * i;
        hout[row * HDIM + c] = xv[i] * rr * mnw[c];
    }
}

__global__ __launch_bounds__(256) void rms_kernel(
    const float* __restrict__ x, const float* __restrict__ w,
    float* __restrict__ out)
{
    __shared__ float sh[9];
    size_t row = blockIdx.x;
    int tid = threadIdx.x;
    const float* xp = x + row * HDIM;
    float v[4]; float ss = 0.f;
#pragma unroll
    for (int i = 0; i < 4; i++) { v[i] = xp[tid + 256 * i]; ss += v[i] * v[i]; }
    ss = block_sum_256(ss, sh);
    float rr = rsqrtf(ss * (1.f / 1024.f) + 1e-6f);
#pragma unroll
    for (int i = 0; i < 4; i++) {
        int c = tid + 256 * i;
        out[row * HDIM + c] = v[i] * rr * w[c];
    }
}

// ---------------------------------------------------------------------------
// Depthwise causal conv (K=4) + SiLU + mask
// ---------------------------------------------------------------------------
__global__ __launch_bounds__(256) void conv_kernel(
    const float* __restrict__ proj, const int* __restrict__ mask,
    const float* __restrict__ cw, const float* __restrict__ cb,
    float* __restrict__ ssm)
{
    int idx = blockIdx.x * 256 + threadIdx.x;
    int d = idx & (DIN - 1);
    int l = (idx >> 11) & (LLEN - 1);
    int b = idx >> 21;
    float acc = cb[d];
#pragma unroll
    for (int j = 0; j < 4; j++) {
        int lp = l - 3 + j;
        if (lp >= 0) {
            float hv = proj[((size_t)(b * LLEN + lp)) * (2 * DIN) + d] *
                       (float)mask[b * LLEN + lp];
            acc = fmaf(hv, cw[d * 4 + j], acc);
        }
    }
    float sv = acc / (1.f + __expf(-acc));
    ssm[(size_t)idx] = sv * (float)mask[b * LLEN + l];
}

// ---------------------------------------------------------------------------
// Selective scan: thread per (b,d), 16-state recurrence, prefetched loads
// ---------------------------------------------------------------------------
__global__ __launch_bounds__(64) void scan_kernel(
    const float* __restrict__ dt, const float* __restrict__ dbc,
    const float* __restrict__ u, const float* __restrict__ proj,
    const float* __restrict__ Alog, const float* __restrict__ Dskip,
    float* __restrict__ outp)
{
    __shared__ float sBC[2][32];
    int b = blockIdx.x >> 5;
    int d = ((blockIdx.x & 31) << 6) + threadIdx.x;
    int t = threadIdx.x;
    float aA[NSTATE];
#pragma unroll
    for (int n = 0; n < NSTATE; n++) aA[n] = -__expf(Alog[d * NSTATE + n]);
    float dsk = Dskip[d];
    float s[NSTATE];
#pragma unroll
    for (int n = 0; n < NSTATE; n++) s[n] = 0.f;

    size_t tokbase = (size_t)b * LLEN;
    if (t < 32) sBC[0][t] = dbc[tokbase * 96 + 64 + t];
    float dtv = dt[tokbase * DIN + d];
    float uv = u[tokbase * DIN + d];
    float gv = proj[tokbase * (2 * DIN) + DIN + d];
    __syncthreads();

    for (int l = 0; l < LLEN; l++) {
        int cur = l & 1;
        float ndt = 0.f, nu = 0.f, ng = 0.f, nbc = 0.f;
        if (l + 1 < LLEN) {
            size_t tk = tokbase + l + 1;
            ndt = dt[tk * DIN + d];
            nu = u[tk * DIN + d];
            ng = proj[tk * (2 * DIN) + DIN + d];
            if (t < 32) nbc = dbc[tk * 96 + 64 + t];
        }
        float c = dtv * uv;
        float y = 0.f;
#pragma unroll
        for (int n = 0; n < NSTATE; n++) {
            float dA = __expf(dtv * aA[n]);
            s[n] = fmaf(dA, s[n], c * sBC[cur][n]);
            y = fmaf(s[n], sBC[cur][16 + n], y);
        }
        float sg = gv / (1.f + __expf(-gv));
        outp[(tokbase + l) * DIN + d] = (y + uv * dsk) * sg;
        if (t < 32 && l + 1 < LLEN) sBC[cur ^ 1][t] = nbc;
        dtv = ndt; uv = nu; gv = ng;
        __syncthreads();
    }
}

// ---------------------------------------------------------------------------
extern "C" void kernel_launch(void* const* d_in, const int* in_sizes, int n_in,
                              void* d_out, int out_size)
{
    const float* hidden = (const float*)d_in[0];
    const int*   mask   = (const int*)d_in[1];
    const float* Wq = (const float*)d_in[2];
    const float* bq = (const float*)d_in[3];
    const float* Wk = (const float*)d_in[4];
    const float* bk = (const float*)d_in[5];
    const float* Wv = (const float*)d_in[6];
    const float* bv = (const float*)d_in[7];
    const float* Wo = (const float*)d_in[8];
    const float* bo = (const float*)d_in[9];
    const float* lnw = (const float*)d_in[10];
    const float* lnb = (const float*)d_in[11];
    const float* mnw = (const float*)d_in[12];
    const float* inpw = (const float*)d_in[13];
    const float* convw = (const float*)d_in[14];
    const float* convb = (const float*)d_in[15];
    const float* xpw = (const float*)d_in[16];
    const float* dtpw = (const float*)d_in[17];
    const float* dtpb = (const float*)d_in[18];
    const float* Alog = (const float*)d_in[19];
    const float* Dsk = (const float*)d_in[20];
    const float* outpw = (const float*)d_in[21];
    const float* fnw = (const float*)d_in[22];
    float* out = (float*)d_out;

    float* buf = nullptr;
    cudaGetSymbolAddress((void**)&buf, g_buf);
    float* qb  = buf;
    float* kb  = buf + U;
    float* vb  = buf + 2 * U;
    float* ctx = buf + 3 * U;
    float* tb  = buf + 4 * U;
    float* x2  = buf + 5 * U;
    float* hb  = buf + 6 * U;
    float* proj = buf + 7 * U;                 // B*L*4096
    float* ssm  = buf + 11 * U;                // B*L*2048
    float* dbc  = buf + 13 * U;                // B*L*96
    float* dt   = dbc + (size_t)BB * LLEN * 96;
    float* scan = dt + 2 * U;
    float* xf   = scan + 2 * U;

    int M = BB * LLEN;
    dim3 thr(256);
    const int MM_SMEM = 2 * 2 * 128 * SMP * 4;   // 40960 B

    cudaFuncSetAttribute(mm_kernel, cudaFuncAttributeMaxDynamicSharedMemorySize, MM_SMEM);
    cudaFuncSetAttribute(attn_kernel, cudaFuncAttributeMaxDynamicSharedMemorySize, QT * LLEN * 4);

    mm_kernel<<<dim3(8, 16), thr, MM_SMEM>>>(hidden, HDIM, Wq, HDIM, bq, nullptr, qb, M, HDIM, HDIM, 0);
    mm_kernel<<<dim3(8, 16), thr, MM_SMEM>>>(hidden, HDIM, Wk, HDIM, bk, nullptr, kb, M, HDIM, HDIM, 0);
    mm_kernel<<<dim3(8, 16), thr, MM_SMEM>>>(hidden, HDIM, Wv, HDIM, bv, nullptr, vb, M, HDIM, HDIM, 0);

    attn_kernel<<<dim3(LLEN / QT, NHEAD, BB), thr, QT * LLEN * 4>>>(qb, kb, vb, mask, ctx);

    mm_kernel<<<dim3(8, 16), thr, MM_SMEM>>>(ctx, HDIM, Wo, HDIM, bo, hidden, tb, M, HDIM, HDIM, 0);
    ln_rms_kernel<<<M, thr>>>(tb, hidden, lnw, lnb, mnw, x2, hb);
    mm_kernel<<<dim3(32, 16), thr, MM_SMEM>>>(hb, HDIM, inpw, HDIM, nullptr, nullptr, proj, M, 2 * DIN, HDIM, 0);
    conv_kernel<<<(BB * LLEN * DIN) / 256, thr>>>(proj, mask, convw, convb, ssm);
    mm_kernel<<<dim3(1, 16), thr, MM_SMEM>>>(ssm, DIN, xpw, DIN, nullptr, nullptr, dbc, M, 96, DIN, 0);
    mm_kernel<<<dim3(16, 16), thr, MM_SMEM>>>(dbc, 96, dtpw, 64, dtpb, nullptr, dt, M, DIN, 64, 1);
    scan_kernel<<<64, 64>>>(dt, dbc, ssm, proj, Alog, Dsk, scan);
    mm_kernel<<<dim3(8, 16), thr, MM_SMEM>>>(scan, DIN, outpw, DIN, nullptr, x2, xf, M, HDIM, DIN, 0);
    rms_kernel<<<M, thr>>>(xf, fnw, out);
}